// round 5
// baseline (speedup 1.0000x reference)
#include <cuda_runtime.h>
#include <cuda_bf16.h>
#include <math.h>
#include <stdint.h>

// Problem constants (fixed shapes)
#define BB 4
#define SS 2048
#define DM 1024
#define NH 16
#define HD 64
#define MROWS (BB * SS)   // 8192

// ---------------- scratch (static __device__, no allocation) ----------------
__device__ float g_q[MROWS * DM];
__device__ float g_k[MROWS * DM];
__device__ float g_v[MROWS * DM];
__device__ float g_attn[MROWS * DM];
__device__ float g_beta[MROWS * NH];
__device__ float g_invrms[MROWS];

// ---------------- tensor-core GEMM: C = epi(A[M,K] @ B[N,K]^T) --------------
// 3xTF32 (hi*hi + hi*lo + lo*hi). Split is done ONCE at smem staging; the
// inner loop is pure LDS + MMA. BM=BN=128, BK=16, 256 threads
// (8 warps: 4 in M x 2 in N). Each warp: 32(M) x 64(N).

#define GBK 16
#define SP 20   // 16 + 4 pad

__device__ __forceinline__ void mma_tf32(float* c, const uint32_t* a,
                                         uint32_t b0, uint32_t b1)
{
    asm volatile(
        "mma.sync.aligned.m16n8k8.row.col.f32.tf32.tf32.f32 "
        "{%0,%1,%2,%3},{%4,%5,%6,%7},{%8,%9},{%0,%1,%2,%3};"
        : "+f"(c[0]), "+f"(c[1]), "+f"(c[2]), "+f"(c[3])
        : "r"(a[0]), "r"(a[1]), "r"(a[2]), "r"(a[3]), "r"(b0), "r"(b1));
}

__device__ __forceinline__ void split_tf32(float x, float& hi, float& lo)
{
    uint32_t h;
    asm("cvt.rna.tf32.f32 %0, %1;" : "=r"(h) : "f"(x));
    hi = __uint_as_float(h);
    float lf = x - hi;
    uint32_t l;
    asm("cvt.rna.tf32.f32 %0, %1;" : "=r"(l) : "f"(lf));
    lo = __uint_as_float(l);
}

// epilogue modes: 0 = none, 1 = silu, 2 = silu + per-64col l2-normalize
// a_scaled: if true, A elements are scaled by invr[row]*rmsw[k] at staging.
__device__ __forceinline__
void mma_gemm_body(const float* __restrict__ A, const float* __restrict__ B,
                   float* __restrict__ C, int epi_mode, int a_scaled,
                   const float* __restrict__ rmsw)
{
    const int K = DM, N = DM;
    __shared__ __align__(16) float Ah[128][SP];
    __shared__ __align__(16) float Al[128][SP];
    __shared__ __align__(16) float Bh[128][SP];
    __shared__ __align__(16) float Bl[128][SP];

    const int tid = threadIdx.x;
    const int lane = tid & 31;
    const int warp = tid >> 5;
    const int warp_m = warp & 3;       // 0..3 -> 32 rows each
    const int warp_n = warp >> 2;      // 0..1 -> 64 cols each
    const int g = lane >> 2;           // groupID 0..7
    const int tg = lane & 3;           // threadID_in_group 0..3

    const int bm0 = blockIdx.y * 128;
    const int bn0 = blockIdx.x * 128;

    // staging mapping: 2 float4 per thread per operand per tile
    int lrow[2], lcg[2];
#pragma unroll
    for (int i = 0; i < 2; i++) {
        int idx = i * 256 + tid;       // 0..511
        lrow[i] = idx >> 2;            // 0..127
        lcg[i] = (idx & 3) << 2;       // 0,4,8,12
    }
    float ainv[2];
#pragma unroll
    for (int i = 0; i < 2; i++)
        ainv[i] = a_scaled ? g_invrms[bm0 + lrow[i]] : 1.f;

    float acc[2][8][4];
#pragma unroll
    for (int mt = 0; mt < 2; mt++)
#pragma unroll
        for (int nt = 0; nt < 8; nt++)
#pragma unroll
            for (int r = 0; r < 4; r++) acc[mt][nt][r] = 0.f;

    // preload tile 0
    float4 pa[2], pb[2];
#pragma unroll
    for (int i = 0; i < 2; i++) {
        pa[i] = *(const float4*)(A + (size_t)(bm0 + lrow[i]) * K + lcg[i]);
        pb[i] = *(const float4*)(B + (size_t)(bn0 + lrow[i]) * K + lcg[i]);
    }

    for (int k0 = 0; k0 < K; k0 += GBK) {
        // commit prefetched tile to smem, splitting hi/lo once
#pragma unroll
        for (int i = 0; i < 2; i++) {
            float av[4] = {pa[i].x, pa[i].y, pa[i].z, pa[i].w};
            if (a_scaled) {
                float4 wv = *(const float4*)(rmsw + k0 + lcg[i]);
                av[0] *= ainv[i] * wv.x; av[1] *= ainv[i] * wv.y;
                av[2] *= ainv[i] * wv.z; av[3] *= ainv[i] * wv.w;
            }
            float h[4], l[4];
#pragma unroll
            for (int c = 0; c < 4; c++) split_tf32(av[c], h[c], l[c]);
            *(float4*)&Ah[lrow[i]][lcg[i]] = make_float4(h[0], h[1], h[2], h[3]);
            *(float4*)&Al[lrow[i]][lcg[i]] = make_float4(l[0], l[1], l[2], l[3]);
            float bv[4] = {pb[i].x, pb[i].y, pb[i].z, pb[i].w};
#pragma unroll
            for (int c = 0; c < 4; c++) split_tf32(bv[c], h[c], l[c]);
            *(float4*)&Bh[lrow[i]][lcg[i]] = make_float4(h[0], h[1], h[2], h[3]);
            *(float4*)&Bl[lrow[i]][lcg[i]] = make_float4(l[0], l[1], l[2], l[3]);
        }
        __syncthreads();

        // prefetch next tile
        if (k0 + GBK < K) {
#pragma unroll
            for (int i = 0; i < 2; i++) {
                pa[i] = *(const float4*)(A + (size_t)(bm0 + lrow[i]) * K + k0 + GBK + lcg[i]);
                pb[i] = *(const float4*)(B + (size_t)(bn0 + lrow[i]) * K + k0 + GBK + lcg[i]);
            }
        }

#pragma unroll
        for (int kk = 0; kk < GBK; kk += 8) {
            uint32_t ah[2][4], al[2][4];
#pragma unroll
            for (int mt = 0; mt < 2; mt++) {
                int mr = warp_m * 32 + mt * 16 + g;
                ah[mt][0] = __float_as_uint(Ah[mr][kk + tg]);
                ah[mt][1] = __float_as_uint(Ah[mr + 8][kk + tg]);
                ah[mt][2] = __float_as_uint(Ah[mr][kk + tg + 4]);
                ah[mt][3] = __float_as_uint(Ah[mr + 8][kk + tg + 4]);
                al[mt][0] = __float_as_uint(Al[mr][kk + tg]);
                al[mt][1] = __float_as_uint(Al[mr + 8][kk + tg]);
                al[mt][2] = __float_as_uint(Al[mr][kk + tg + 4]);
                al[mt][3] = __float_as_uint(Al[mr + 8][kk + tg + 4]);
            }
#pragma unroll
            for (int nt = 0; nt < 8; nt++) {
                int nr = warp_n * 64 + nt * 8 + g;
                uint32_t bh0 = __float_as_uint(Bh[nr][kk + tg]);
                uint32_t bh1 = __float_as_uint(Bh[nr][kk + tg + 4]);
                uint32_t bl0 = __float_as_uint(Bl[nr][kk + tg]);
                uint32_t bl1 = __float_as_uint(Bl[nr][kk + tg + 4]);
#pragma unroll
                for (int mt = 0; mt < 2; mt++) {
                    mma_tf32(acc[mt][nt], ah[mt], bh0, bh1);  // hi*hi
                    mma_tf32(acc[mt][nt], ah[mt], bl0, bl1);  // hi*lo
                    mma_tf32(acc[mt][nt], al[mt], bh0, bh1);  // lo*hi
                }
            }
        }
        __syncthreads();
    }

    // epilogue
    float v[2][8][4];
#pragma unroll
    for (int mt = 0; mt < 2; mt++)
#pragma unroll
        for (int nt = 0; nt < 8; nt++)
#pragma unroll
            for (int r = 0; r < 4; r++) {
                float x = acc[mt][nt][r];
                if (epi_mode >= 1) x = x / (1.f + expf(-x));
                v[mt][nt][r] = x;
            }

    if (epi_mode == 2) {
        // l2-normalize each row's 64-col head segment (whole warp_n half)
#pragma unroll
        for (int mt = 0; mt < 2; mt++) {
            float s0 = 0.f, s1 = 0.f;   // row g, row g+8
#pragma unroll
            for (int nt = 0; nt < 8; nt++) {
                s0 = fmaf(v[mt][nt][0], v[mt][nt][0],
                     fmaf(v[mt][nt][1], v[mt][nt][1], s0));
                s1 = fmaf(v[mt][nt][2], v[mt][nt][2],
                     fmaf(v[mt][nt][3], v[mt][nt][3], s1));
            }
            s0 += __shfl_xor_sync(0xffffffffu, s0, 1);
            s0 += __shfl_xor_sync(0xffffffffu, s0, 2);
            s1 += __shfl_xor_sync(0xffffffffu, s1, 1);
            s1 += __shfl_xor_sync(0xffffffffu, s1, 2);
            float i0 = 1.f / (sqrtf(s0) + 1e-6f);
            float i1 = 1.f / (sqrtf(s1) + 1e-6f);
#pragma unroll
            for (int nt = 0; nt < 8; nt++) {
                v[mt][nt][0] *= i0; v[mt][nt][1] *= i0;
                v[mt][nt][2] *= i1; v[mt][nt][3] *= i1;
            }
        }
    }

#pragma unroll
    for (int mt = 0; mt < 2; mt++)
#pragma unroll
        for (int nt = 0; nt < 8; nt++) {
            int row0 = bm0 + warp_m * 32 + mt * 16 + g;
            int cb = bn0 + warp_n * 64 + nt * 8 + 2 * tg;
            *(float2*)(C + (size_t)row0 * N + cb)       = make_float2(v[mt][nt][0], v[mt][nt][1]);
            *(float2*)(C + (size_t)(row0 + 8) * N + cb) = make_float2(v[mt][nt][2], v[mt][nt][3]);
        }
}

// Fused QKV: blockIdx.z selects (Wq->g_q silu+l2, Wk->g_k silu+l2, Wv->g_v silu)
__global__ __launch_bounds__(256, 2)
void mma_qkv(const float* __restrict__ x,
             const float* __restrict__ Wq,
             const float* __restrict__ Wk,
             const float* __restrict__ Wv)
{
    if (blockIdx.z == 0)      mma_gemm_body(x, Wq, g_q, 2, 0, (const float*)0);
    else if (blockIdx.z == 1) mma_gemm_body(x, Wk, g_k, 2, 0, (const float*)0);
    else                      mma_gemm_body(x, Wv, g_v, 1, 0, (const float*)0);
}

// Output projection with fused RMSNorm scaling on A: (attn*invrms*rmsw) @ Wo^T
__global__ __launch_bounds__(256, 2)
void mma_o(const float* __restrict__ Wo, const float* __restrict__ rmsw,
           float* __restrict__ outp)
{
    mma_gemm_body(g_attn, Wo, outp, 0, 1, rmsw);
}

// ---------------- beta: sigmoid(x @ Wbeta^T), (8192,16) ---------------------
__global__ __launch_bounds__(512)
void beta_kernel(const float* __restrict__ x, const float* __restrict__ Wb)
{
    __shared__ __align__(16) float sx[DM];
    const int row = blockIdx.x;
    const int tid = threadIdx.x;
    {
        float2 t = *(const float2*)(x + (size_t)row * DM + 2 * tid);
        *(float2*)(sx + 2 * tid) = t;
    }
    __syncthreads();
    const int w = tid >> 5, l = tid & 31;   // warp w -> head w (16 warps)
    const float* wrow = Wb + (size_t)w * DM;
    float s = 0.f;
#pragma unroll
    for (int i = 0; i < 8; i++) {
        int kb = i * 128 + l * 4;
        float4 wv = *(const float4*)(wrow + kb);
        float4 xv = *(const float4*)(sx + kb);
        s += wv.x * xv.x + wv.y * xv.y + wv.z * xv.z + wv.w * xv.w;
    }
#pragma unroll
    for (int o = 16; o; o >>= 1) s += __shfl_xor_sync(0xffffffffu, s, o);
    if (l == 0) g_beta[(size_t)row * NH + w] = 1.f / (1.f + expf(-s));
}

// ---------------- per-row inverse RMS (for fused rmsnorm in mma_o) ----------
__global__ __launch_bounds__(256)
void row_rms_kernel()
{
    __shared__ float red[8];
    const int row = blockIdx.x;
    const int tid = threadIdx.x;
    const int l = tid & 31, wd = tid >> 5;
    float4 x = ((const float4*)(g_attn + (size_t)row * DM))[tid];
    float s = x.x * x.x + x.y * x.y + x.z * x.z + x.w * x.w;
#pragma unroll
    for (int o = 16; o; o >>= 1) s += __shfl_xor_sync(0xffffffffu, s, o);
    if (l == 0) red[wd] = s;
    __syncthreads();
    if (tid == 0) {
        float t = red[0] + red[1] + red[2] + red[3] + red[4] + red[5] + red[6] + red[7];
        g_invrms[row] = rsqrtf(t * (1.f / DM) + 1e-6f);
    }
}

// ---------------- delta-rule recurrence -------------------------------------
// One CTA per (b, head). 128 threads. M (64x64) kept twice in registers.
// Dot-product chains broken into 4 accumulators (8-deep FMA chains).
__global__ __launch_bounds__(128, 1)
void recurrence_kernel()
{
    const int b = blockIdx.x >> 4;
    const int n = blockIdx.x & 15;
    const int tid = threadIdx.x;
    const int col = tid >> 1;
    const int half = tid & 1;
    const int h0 = half * 32;
    const int wid = tid >> 5, lane = tid & 31;

    __shared__ __align__(16) float stage[2][200]; // [0:64)=q [64:128)=k [128:192)=v [192]=beta
    __shared__ __align__(16) float sdelta[64];

    float C[32], R[32];
#pragma unroll
    for (int i = 0; i < 32; i++) { C[i] = 0.f; R[i] = 0.f; }

    const size_t base0 = ((size_t)(b * SS) * NH + n) * HD;  // step stride = NH*HD = 1024
    const size_t bbase = (size_t)(b * SS) * NH + n;          // beta step stride = 16

    // stage s = 0
    if (wid == 0) *(float2*)&stage[0][0 + 2 * lane]   = *(const float2*)(g_q + base0 + 2 * lane);
    else if (wid == 1) *(float2*)&stage[0][64 + 2 * lane]  = *(const float2*)(g_k + base0 + 2 * lane);
    else if (wid == 2) *(float2*)&stage[0][128 + 2 * lane] = *(const float2*)(g_v + base0 + 2 * lane);
    else if (lane == 0) stage[0][192] = g_beta[bbase];
    __syncthreads();

    for (int s = 0; s < SS; s++) {
        const int p = s & 1;
        // prefetch s+1 into registers
        float2 pre = make_float2(0.f, 0.f);
        float preb = 0.f;
        const bool has = (s + 1 < SS);
        if (has) {
            size_t bn2 = base0 + (size_t)(s + 1) * (NH * HD);
            if (wid == 0) pre = *(const float2*)(g_q + bn2 + 2 * lane);
            else if (wid == 1) pre = *(const float2*)(g_k + bn2 + 2 * lane);
            else if (wid == 2) pre = *(const float2*)(g_v + bn2 + 2 * lane);
            else if (lane == 0) preb = g_beta[bbase + (size_t)(s + 1) * NH];
        }

        // phase 1: retrieved[col] = sum_d M[col][d] * k[d]  (4 accumulators)
        float pa = 0.f, pb = 0.f, pc = 0.f, pd = 0.f;
#pragma unroll
        for (int j = 0; j < 8; j++) {
            float4 kv = *(const float4*)&stage[p][64 + h0 + 4 * j];
            pa = fmaf(R[4*j],   kv.x, pa);
            pb = fmaf(R[4*j+1], kv.y, pb);
            pc = fmaf(R[4*j+2], kv.z, pc);
            pd = fmaf(R[4*j+3], kv.w, pd);
        }
        float partial = (pa + pb) + (pc + pd);
        partial += __shfl_xor_sync(0xffffffffu, partial, 1);
        const float bs = stage[p][192];
        const float delta = stage[p][128 + col] - partial;   // v[col] - retrieved[col]
        if (half == 0) sdelta[col] = delta;
        __syncthreads();

        // phase 2: out[col] = sum_h q[h]*M[h][col]; M[h][col] += bs*k[h]*delta[col]
        const float bd = bs * delta;
        float qa = 0.f, qb = 0.f, qc = 0.f, qd = 0.f;
#pragma unroll
        for (int j = 0; j < 8; j++) {
            float4 qv = *(const float4*)&stage[p][h0 + 4 * j];
            float4 kv = *(const float4*)&stage[p][64 + h0 + 4 * j];
            qa = fmaf(qv.x, C[4*j],   qa);
            qb = fmaf(qv.y, C[4*j+1], qb);
            qc = fmaf(qv.z, C[4*j+2], qc);
            qd = fmaf(qv.w, C[4*j+3], qd);
            C[4*j]   = fmaf(kv.x, bd, C[4*j]);
            C[4*j+1] = fmaf(kv.y, bd, C[4*j+1]);
            C[4*j+2] = fmaf(kv.z, bd, C[4*j+2]);
            C[4*j+3] = fmaf(kv.w, bd, C[4*j+3]);
        }
        // row update: M[col][d] += bs*k[col]*delta[d]
        const float bk = bs * stage[p][64 + col];
#pragma unroll
        for (int j = 0; j < 8; j++) {
            float4 dv = *(const float4*)&sdelta[h0 + 4 * j];
            R[4*j]   = fmaf(bk, dv.x, R[4*j]);
            R[4*j+1] = fmaf(bk, dv.y, R[4*j+1]);
            R[4*j+2] = fmaf(bk, dv.z, R[4*j+2]);
            R[4*j+3] = fmaf(bk, dv.w, R[4*j+3]);
        }
        float acc = (qa + qb) + (qc + qd);
        acc += __shfl_xor_sync(0xffffffffu, acc, 1);
        if (half == 0) g_attn[base0 + (size_t)s * (NH * HD) + col] = acc;

        // stash prefetch into the other buffer
        if (has) {
            if (wid == 0) *(float2*)&stage[p ^ 1][0 + 2 * lane]   = pre;
            else if (wid == 1) *(float2*)&stage[p ^ 1][64 + 2 * lane]  = pre;
            else if (wid == 2) *(float2*)&stage[p ^ 1][128 + 2 * lane] = pre;
            else if (lane == 0) stage[p ^ 1][192] = preb;
        }
        __syncthreads();
    }
}

// ---------------- launch (pure kernel launches, no runtime API) -------------
extern "C" void kernel_launch(void* const* d_in, const int* in_sizes, int n_in,
                              void* d_out, int out_size)
{
    const float* x    = (const float*)d_in[0];
    const float* Wq   = (const float*)d_in[1];
    const float* Wk   = (const float*)d_in[2];
    const float* Wv   = (const float*)d_in[3];
    const float* Wo   = (const float*)d_in[4];
    const float* Wb   = (const float*)d_in[5];
    const float* rmsw = (const float*)d_in[6];
    float* outp = (float*)d_out;

    dim3 qkv_grid(DM / 128, MROWS / 128, 3);   // (8, 64, 3)
    dim3 o_grid(DM / 128, MROWS / 128);        // (8, 64)
    dim3 gblk(256);

    // projections: fused SiLU + l2norm(q,k) on tensor cores
    mma_qkv<<<qkv_grid, gblk>>>(x, Wq, Wk, Wv);
    beta_kernel<<<MROWS, 512>>>(x, Wb);
    // sequential delta-rule recurrence (64 independent states)
    recurrence_kernel<<<BB * NH, 128>>>();
    // per-row inv RMS, then output projection with fused rmsnorm scaling
    row_rms_kernel<<<MROWS, 256>>>();
    mma_o<<<o_grid, gblk>>>(Wo, rmsw, outp);
}

// round 7
// speedup vs baseline: 1.1996x; 1.1996x over previous
#include <cuda_runtime.h>
#include <cuda_bf16.h>
#include <math.h>
#include <stdint.h>

// Problem constants (fixed shapes)
#define BB 4
#define SS 2048
#define DM 1024
#define NH 16
#define HD 64
#define MROWS (BB * SS)   // 8192

// ---------------- scratch (static __device__, no allocation) ----------------
__device__ float g_q[MROWS * DM];
__device__ float g_k[MROWS * DM];
__device__ float g_v[MROWS * DM];
__device__ float g_attn[MROWS * DM];
__device__ float g_beta[MROWS * NH];
__device__ float g_invrms[MROWS];

// bf16 hi/lo split planes
__device__ __nv_bfloat16 g_Whi[4 * DM * DM];
__device__ __nv_bfloat16 g_Wlo[4 * DM * DM];
__device__ __nv_bfloat16 g_xhi[MROWS * DM];
__device__ __nv_bfloat16 g_xlo[MROWS * DM];
__device__ __nv_bfloat16 g_ahi[MROWS * DM];
__device__ __nv_bfloat16 g_alo[MROWS * DM];

// ---------------- bf16 split helper -----------------------------------------
__device__ __forceinline__ void bsplit4(float4 v, uint32_t* hi, uint32_t* lo)
{
    __nv_bfloat162 h01 = __floats2bfloat162_rn(v.x, v.y);
    __nv_bfloat162 h23 = __floats2bfloat162_rn(v.z, v.w);
    float2 f01 = __bfloat1622float2(h01);
    float2 f23 = __bfloat1622float2(h23);
    __nv_bfloat162 l01 = __floats2bfloat162_rn(v.x - f01.x, v.y - f01.y);
    __nv_bfloat162 l23 = __floats2bfloat162_rn(v.z - f23.x, v.w - f23.y);
    hi[0] = *(uint32_t*)&h01; hi[1] = *(uint32_t*)&h23;
    lo[0] = *(uint32_t*)&l01; lo[1] = *(uint32_t*)&l23;
}

// ---------------- one-shot split kernels -------------------------------------
__global__ __launch_bounds__(256)
void split_w_kernel(const float* __restrict__ Wq, const float* __restrict__ Wk,
                    const float* __restrict__ Wv, const float* __restrict__ Wo)
{
    const float* W = (blockIdx.y == 0) ? Wq : (blockIdx.y == 1) ? Wk
                   : (blockIdx.y == 2) ? Wv : Wo;
    size_t i = (size_t)blockIdx.x * 256 + threadIdx.x;    // float4 idx, 262144
    float4 v = ((const float4*)W)[i];
    uint32_t hi[2], lo[2];
    bsplit4(v, hi, lo);
    size_t base = (size_t)blockIdx.y * (DM * DM / 4);
    ((uint2*)g_Whi)[base + i] = make_uint2(hi[0], hi[1]);
    ((uint2*)g_Wlo)[base + i] = make_uint2(lo[0], lo[1]);
}

__global__ __launch_bounds__(256)
void split_x_kernel(const float* __restrict__ x)
{
    size_t i = (size_t)blockIdx.x * 256 + threadIdx.x;    // float4 idx, 2M
    float4 v = ((const float4*)x)[i];
    uint32_t hi[2], lo[2];
    bsplit4(v, hi, lo);
    ((uint2*)g_xhi)[i] = make_uint2(hi[0], hi[1]);
    ((uint2*)g_xlo)[i] = make_uint2(lo[0], lo[1]);
}

// attn * invrms[row] * rmsw[col], then split (fused rmsnorm)
__global__ __launch_bounds__(256)
void split_attn_kernel(const float* __restrict__ rmsw)
{
    size_t i = (size_t)blockIdx.x * 256 + threadIdx.x;    // float4 idx, 2M
    int row = (int)(i >> 8);                              // 256 float4 per row
    int c4 = (int)(i & 255);
    float4 v = ((const float4*)g_attn)[i];
    float s = g_invrms[row];
    float4 w = ((const float4*)rmsw)[c4];
    v.x *= s * w.x; v.y *= s * w.y; v.z *= s * w.z; v.w *= s * w.w;
    uint32_t hi[2], lo[2];
    bsplit4(v, hi, lo);
    ((uint2*)g_ahi)[i] = make_uint2(hi[0], hi[1]);
    ((uint2*)g_alo)[i] = make_uint2(lo[0], lo[1]);
}

// ---------------- tensor-core GEMM: C = epi(A[M,K] @ B[N,K]^T) --------------
// bf16x3 (hi*hi + hi*lo + lo*hi) with pre-split operands. Staging is pure
// LDG.128 -> STS.128. BM=BN=128, BK=16, 256 threads (8 warps: 4M x 2N).

#define RBK 16
#define RBP 24   // padded bf16 row: 48B -> conflict-free frag LDS

__device__ __forceinline__ void mma_bf16(float* c, const uint32_t* a,
                                         uint32_t b0, uint32_t b1)
{
    asm volatile(
        "mma.sync.aligned.m16n8k16.row.col.f32.bf16.bf16.f32 "
        "{%0,%1,%2,%3},{%4,%5,%6,%7},{%8,%9},{%0,%1,%2,%3};"
        : "+f"(c[0]), "+f"(c[1]), "+f"(c[2]), "+f"(c[3])
        : "r"(a[0]), "r"(a[1]), "r"(a[2]), "r"(a[3]), "r"(b0), "r"(b1));
}

// epilogue modes: 0 = none, 1 = silu, 2 = silu + per-64col l2-normalize
__device__ __forceinline__
void mma_gemm_body(const __nv_bfloat16* __restrict__ Ahi,
                   const __nv_bfloat16* __restrict__ Alo,
                   const __nv_bfloat16* __restrict__ Bhi,
                   const __nv_bfloat16* __restrict__ Blo,
                   float* __restrict__ C, int epi_mode)
{
    const int K = DM, N = DM;
    __shared__ __align__(16) __nv_bfloat16 Ah[128][RBP];
    __shared__ __align__(16) __nv_bfloat16 Al[128][RBP];
    __shared__ __align__(16) __nv_bfloat16 Bh[128][RBP];
    __shared__ __align__(16) __nv_bfloat16 Bl[128][RBP];

    const int tid = threadIdx.x;
    const int lane = tid & 31;
    const int warp = tid >> 5;
    const int warp_m = warp & 3;
    const int warp_n = warp >> 2;
    const int g = lane >> 2;
    const int tg = lane & 3;

    const int bm0 = blockIdx.y * 128;
    const int bn0 = blockIdx.x * 128;

    // staging map: thread -> (row, 8-elem half)
    const int srow = tid >> 1;
    const int shalf = (tid & 1) * 8;
    const size_t aoff = (size_t)(bm0 + srow) * K + shalf;
    const size_t boff = (size_t)(bn0 + srow) * K + shalf;

    float acc[2][8][4];
#pragma unroll
    for (int mt = 0; mt < 2; mt++)
#pragma unroll
        for (int nt = 0; nt < 8; nt++)
#pragma unroll
            for (int r = 0; r < 4; r++) acc[mt][nt][r] = 0.f;

    // preload tile 0
    uint4 vah = *(const uint4*)(Ahi + aoff);
    uint4 val = *(const uint4*)(Alo + aoff);
    uint4 vbh = *(const uint4*)(Bhi + boff);
    uint4 vbl = *(const uint4*)(Blo + boff);

    for (int k0 = 0; k0 < K; k0 += RBK) {
        *(uint4*)&Ah[srow][shalf] = vah;
        *(uint4*)&Al[srow][shalf] = val;
        *(uint4*)&Bh[srow][shalf] = vbh;
        *(uint4*)&Bl[srow][shalf] = vbl;
        __syncthreads();

        if (k0 + RBK < K) {
            vah = *(const uint4*)(Ahi + aoff + k0 + RBK);
            val = *(const uint4*)(Alo + aoff + k0 + RBK);
            vbh = *(const uint4*)(Bhi + boff + k0 + RBK);
            vbl = *(const uint4*)(Blo + boff + k0 + RBK);
        }

        uint32_t ah[2][4], al[2][4];
#pragma unroll
        for (int mt = 0; mt < 2; mt++) {
            int mr = warp_m * 32 + mt * 16 + g;
            ah[mt][0] = *(const uint32_t*)&Ah[mr][2 * tg];
            ah[mt][1] = *(const uint32_t*)&Ah[mr + 8][2 * tg];
            ah[mt][2] = *(const uint32_t*)&Ah[mr][8 + 2 * tg];
            ah[mt][3] = *(const uint32_t*)&Ah[mr + 8][8 + 2 * tg];
            al[mt][0] = *(const uint32_t*)&Al[mr][2 * tg];
            al[mt][1] = *(const uint32_t*)&Al[mr + 8][2 * tg];
            al[mt][2] = *(const uint32_t*)&Al[mr][8 + 2 * tg];
            al[mt][3] = *(const uint32_t*)&Al[mr + 8][8 + 2 * tg];
        }
#pragma unroll
        for (int nt = 0; nt < 8; nt++) {
            int nr = warp_n * 64 + nt * 8 + g;
            uint32_t bh0 = *(const uint32_t*)&Bh[nr][2 * tg];
            uint32_t bh1 = *(const uint32_t*)&Bh[nr][8 + 2 * tg];
            uint32_t bl0 = *(const uint32_t*)&Bl[nr][2 * tg];
            uint32_t bl1 = *(const uint32_t*)&Bl[nr][8 + 2 * tg];
#pragma unroll
            for (int mt = 0; mt < 2; mt++) {
                mma_bf16(acc[mt][nt], ah[mt], bh0, bh1);  // hi*hi
                mma_bf16(acc[mt][nt], ah[mt], bl0, bl1);  // hi*lo
                mma_bf16(acc[mt][nt], al[mt], bh0, bh1);  // lo*hi
            }
        }
        __syncthreads();
    }

    // epilogue
    float v[2][8][4];
#pragma unroll
    for (int mt = 0; mt < 2; mt++)
#pragma unroll
        for (int nt = 0; nt < 8; nt++)
#pragma unroll
            for (int r = 0; r < 4; r++) {
                float x = acc[mt][nt][r];
                if (epi_mode >= 1) x = x / (1.f + expf(-x));
                v[mt][nt][r] = x;
            }

    if (epi_mode == 2) {
        // l2-normalize each row's 64-col head segment (whole warp_n half)
#pragma unroll
        for (int mt = 0; mt < 2; mt++) {
            float s0 = 0.f, s1 = 0.f;   // row g, row g+8
#pragma unroll
            for (int nt = 0; nt < 8; nt++) {
                s0 = fmaf(v[mt][nt][0], v[mt][nt][0],
                     fmaf(v[mt][nt][1], v[mt][nt][1], s0));
                s1 = fmaf(v[mt][nt][2], v[mt][nt][2],
                     fmaf(v[mt][nt][3], v[mt][nt][3], s1));
            }
            s0 += __shfl_xor_sync(0xffffffffu, s0, 1);
            s0 += __shfl_xor_sync(0xffffffffu, s0, 2);
            s1 += __shfl_xor_sync(0xffffffffu, s1, 1);
            s1 += __shfl_xor_sync(0xffffffffu, s1, 2);
            float i0 = 1.f / (sqrtf(s0) + 1e-6f);
            float i1 = 1.f / (sqrtf(s1) + 1e-6f);
#pragma unroll
            for (int nt = 0; nt < 8; nt++) {
                v[mt][nt][0] *= i0; v[mt][nt][1] *= i0;
                v[mt][nt][2] *= i1; v[mt][nt][3] *= i1;
            }
        }
    }

#pragma unroll
    for (int mt = 0; mt < 2; mt++)
#pragma unroll
        for (int nt = 0; nt < 8; nt++) {
            int row0 = bm0 + warp_m * 32 + mt * 16 + g;
            int cb = bn0 + warp_n * 64 + nt * 8 + 2 * tg;
            *(float2*)(C + (size_t)row0 * N + cb)       = make_float2(v[mt][nt][0], v[mt][nt][1]);
            *(float2*)(C + (size_t)(row0 + 8) * N + cb) = make_float2(v[mt][nt][2], v[mt][nt][3]);
        }
}

// Fused QKV: blockIdx.z selects (Wq->g_q silu+l2, Wk->g_k silu+l2, Wv->g_v silu)
__global__ __launch_bounds__(256, 2)
void mma_qkv()
{
    const size_t wb = (size_t)blockIdx.z * DM * DM;
    if (blockIdx.z == 0)      mma_gemm_body(g_xhi, g_xlo, g_Whi + wb, g_Wlo + wb, g_q, 2);
    else if (blockIdx.z == 1) mma_gemm_body(g_xhi, g_xlo, g_Whi + wb, g_Wlo + wb, g_k, 2);
    else                      mma_gemm_body(g_xhi, g_xlo, g_Whi + wb, g_Wlo + wb, g_v, 1);
}

// Output projection: (pre-scaled attn) @ Wo^T -> out
__global__ __launch_bounds__(256, 2)
void mma_o(float* __restrict__ outp)
{
    const size_t wb = (size_t)3 * DM * DM;
    mma_gemm_body(g_ahi, g_alo, g_Whi + wb, g_Wlo + wb, outp, 0);
}

// ---------------- beta: sigmoid(x @ Wbeta^T), (8192,16) ---------------------
__global__ __launch_bounds__(512)
void beta_kernel(const float* __restrict__ x, const float* __restrict__ Wb)
{
    __shared__ __align__(16) float sx[DM];
    const int row = blockIdx.x;
    const int tid = threadIdx.x;
    {
        float2 t = *(const float2*)(x + (size_t)row * DM + 2 * tid);
        *(float2*)(sx + 2 * tid) = t;
    }
    __syncthreads();
    const int w = tid >> 5, l = tid & 31;   // warp w -> head w (16 warps)
    const float* wrow = Wb + (size_t)w * DM;
    float s = 0.f;
#pragma unroll
    for (int i = 0; i < 8; i++) {
        int kb = i * 128 + l * 4;
        float4 wv = *(const float4*)(wrow + kb);
        float4 xv = *(const float4*)(sx + kb);
        s += wv.x * xv.x + wv.y * xv.y + wv.z * xv.z + wv.w * xv.w;
    }
#pragma unroll
    for (int o = 16; o; o >>= 1) s += __shfl_xor_sync(0xffffffffu, s, o);
    if (l == 0) g_beta[(size_t)row * NH + w] = 1.f / (1.f + expf(-s));
}

// ---------------- per-row inverse RMS ----------------------------------------
__global__ __launch_bounds__(256)
void row_rms_kernel()
{
    __shared__ float red[8];
    const int row = blockIdx.x;
    const int tid = threadIdx.x;
    const int l = tid & 31, wd = tid >> 5;
    float4 x = ((const float4*)(g_attn + (size_t)row * DM))[tid];
    float s = x.x * x.x + x.y * x.y + x.z * x.z + x.w * x.w;
#pragma unroll
    for (int o = 16; o; o >>= 1) s += __shfl_xor_sync(0xffffffffu, s, o);
    if (l == 0) red[wd] = s;
    __syncthreads();
    if (tid == 0) {
        float t = red[0] + red[1] + red[2] + red[3] + red[4] + red[5] + red[6] + red[7];
        g_invrms[row] = rsqrtf(t * (1.f / DM) + 1e-6f);
    }
}

// ---------------- delta-rule recurrence -------------------------------------
// One CTA per (b, head). 128 threads. M (64x64) kept twice in registers.
__global__ __launch_bounds__(128, 1)
void recurrence_kernel()
{
    const int b = blockIdx.x >> 4;
    const int n = blockIdx.x & 15;
    const int tid = threadIdx.x;
    const int col = tid >> 1;
    const int half = tid & 1;
    const int h0 = half * 32;
    const int wid = tid >> 5, lane = tid & 31;

    __shared__ __align__(16) float stage[2][200]; // [0:64)=q [64:128)=k [128:192)=v [192]=beta
    __shared__ __align__(16) float sdelta[64];

    float C[32], R[32];
#pragma unroll
    for (int i = 0; i < 32; i++) { C[i] = 0.f; R[i] = 0.f; }

    const size_t base0 = ((size_t)(b * SS) * NH + n) * HD;
    const size_t bbase = (size_t)(b * SS) * NH + n;

    if (wid == 0) *(float2*)&stage[0][0 + 2 * lane]   = *(const float2*)(g_q + base0 + 2 * lane);
    else if (wid == 1) *(float2*)&stage[0][64 + 2 * lane]  = *(const float2*)(g_k + base0 + 2 * lane);
    else if (wid == 2) *(float2*)&stage[0][128 + 2 * lane] = *(const float2*)(g_v + base0 + 2 * lane);
    else if (lane == 0) stage[0][192] = g_beta[bbase];
    __syncthreads();

    for (int s = 0; s < SS; s++) {
        const int p = s & 1;
        float2 pre = make_float2(0.f, 0.f);
        float preb = 0.f;
        const bool has = (s + 1 < SS);
        if (has) {
            size_t bn2 = base0 + (size_t)(s + 1) * (NH * HD);
            if (wid == 0) pre = *(const float2*)(g_q + bn2 + 2 * lane);
            else if (wid == 1) pre = *(const float2*)(g_k + bn2 + 2 * lane);
            else if (wid == 2) pre = *(const float2*)(g_v + bn2 + 2 * lane);
            else if (lane == 0) preb = g_beta[bbase + (size_t)(s + 1) * NH];
        }

        // phase 1: retrieved[col] = sum_d M[col][d] * k[d]
        float pa = 0.f, pb = 0.f, pc = 0.f, pd = 0.f;
#pragma unroll
        for (int j = 0; j < 8; j++) {
            float4 kv = *(const float4*)&stage[p][64 + h0 + 4 * j];
            pa = fmaf(R[4*j],   kv.x, pa);
            pb = fmaf(R[4*j+1], kv.y, pb);
            pc = fmaf(R[4*j+2], kv.z, pc);
            pd = fmaf(R[4*j+3], kv.w, pd);
        }
        float partial = (pa + pb) + (pc + pd);
        partial += __shfl_xor_sync(0xffffffffu, partial, 1);
        const float bs = stage[p][192];
        const float delta = stage[p][128 + col] - partial;
        if (half == 0) sdelta[col] = delta;
        __syncthreads();

        // phase 2: out[col] = sum_h q[h]*M[h][col]; M[h][col] += bs*k[h]*delta[col]
        const float bd = bs * delta;
        float qa = 0.f, qb = 0.f, qc = 0.f, qd = 0.f;
#pragma unroll
        for (int j = 0; j < 8; j++) {
            float4 qv = *(const float4*)&stage[p][h0 + 4 * j];
            float4 kv = *(const float4*)&stage[p][64 + h0 + 4 * j];
            qa = fmaf(qv.x, C[4*j],   qa);
            qb = fmaf(qv.y, C[4*j+1], qb);
            qc = fmaf(qv.z, C[4*j+2], qc);
            qd = fmaf(qv.w, C[4*j+3], qd);
            C[4*j]   = fmaf(kv.x, bd, C[4*j]);
            C[4*j+1] = fmaf(kv.y, bd, C[4*j+1]);
            C[4*j+2] = fmaf(kv.z, bd, C[4*j+2]);
            C[4*j+3] = fmaf(kv.w, bd, C[4*j+3]);
        }
        const float bk = bs * stage[p][64 + col];
#pragma unroll
        for (int j = 0; j < 8; j++) {
            float4 dv = *(const float4*)&sdelta[h0 + 4 * j];
            R[4*j]   = fmaf(bk, dv.x, R[4*j]);
            R[4*j+1] = fmaf(bk, dv.y, R[4*j+1]);
            R[4*j+2] = fmaf(bk, dv.z, R[4*j+2]);
            R[4*j+3] = fmaf(bk, dv.w, R[4*j+3]);
        }
        float acc = (qa + qb) + (qc + qd);
        acc += __shfl_xor_sync(0xffffffffu, acc, 1);
        if (half == 0) g_attn[base0 + (size_t)s * (NH * HD) + col] = acc;

        if (has) {
            if (wid == 0) *(float2*)&stage[p ^ 1][0 + 2 * lane]   = pre;
            else if (wid == 1) *(float2*)&stage[p ^ 1][64 + 2 * lane]  = pre;
            else if (wid == 2) *(float2*)&stage[p ^ 1][128 + 2 * lane] = pre;
            else if (lane == 0) stage[p ^ 1][192] = preb;
        }
        __syncthreads();
    }
}

// ---------------- launch (pure kernel launches, no runtime API) -------------
extern "C" void kernel_launch(void* const* d_in, const int* in_sizes, int n_in,
                              void* d_out, int out_size)
{
    const float* x    = (const float*)d_in[0];
    const float* Wq   = (const float*)d_in[1];
    const float* Wk   = (const float*)d_in[2];
    const float* Wv   = (const float*)d_in[3];
    const float* Wo   = (const float*)d_in[4];
    const float* Wb   = (const float*)d_in[5];
    const float* rmsw = (const float*)d_in[6];
    float* outp = (float*)d_out;

    // one-shot bf16 hi/lo splits
    split_w_kernel<<<dim3(DM * DM / 4 / 256, 4), 256>>>(Wq, Wk, Wv, Wo);
    split_x_kernel<<<MROWS * DM / 4 / 256, 256>>>(x);

    // projections: fused SiLU + l2norm(q,k) on tensor cores (bf16x3)
    mma_qkv<<<dim3(DM / 128, MROWS / 128, 3), 256>>>();
    beta_kernel<<<MROWS, 512>>>(x, Wb);

    // sequential delta-rule recurrence (64 independent states)
    recurrence_kernel<<<BB * NH, 128>>>();

    // rmsnorm fused into attn split, then output projection
    row_rms_kernel<<<MROWS, 256>>>();
    split_attn_kernel<<<MROWS * DM / 4 / 256, 256>>>(rmsw);
    mma_o<<<dim3(DM / 128, MROWS / 128), 256>>>(outp);
}